// round 12
// baseline (speedup 1.0000x reference)
#include <cuda_runtime.h>
#include <cuda_bf16.h>

// Balloon-Windkessel BOLD, explicit Euler, T=1000 steps, B=16384 sims.
// R12 = R9 arithmetic (bit-identical; rel_err 1.140145e-4) with the readout
// LAGGED BY ONE FULL CHUNK (20 steps):
//  - per step, (v2,q2) go to register arrays; the PREVIOUS chunk's readout
//    (rcp + 4 FMA + STG) and the NEXT-next chunk's noise LDG are interleaved
//    into the same unrolled iteration as pure gap-filler work.
//  - rationale: R7-R11 proved per-warp time (~72 cyc/step) is invariant to
//    op count and warp count -> exposed dependency stalls. This gives the
//    in-order scheduler ~8 independent slots per step to issue inside the
//    s-chain/Horner latency bubbles.
// All state ops and readout ops identical bits to R9, just reordered.

#define DT_C        0.01f
#define V0_C        0.02f
#define NOISE_AMP_C 0.01f
#define BATCH_C     16384

__device__ __forceinline__ float fast_rcp(float x) {
    float r; asm("rcp.approx.f32 %0, %1;" : "=f"(r) : "f"(x)); return r;
}

struct BWState {
    float s, f, v, q;
    float G;    // G(f) for current f (staged)
    float in1;  // fma(-mu, f-1, -sigma*s)   (staged)
    float fv;   // f - v                      (staged)
    float qd;   // G - q                      (staged)
};

struct BWConst {
    float sigma, mu, c_vl;
    float C0, C1, C2, C3;        // readout constants
    float g0, g1, g2, g3, g4;    // G(u) Taylor coefficients (deg 4)
};

// State front: identical ops to R9's bw_step minus the readout.
__device__ __forceinline__ float2 bw_front(BWState& st, const BWConst& C, float z)
{
    const float s2 = fmaf(DT_C, fmaf(NOISE_AMP_C, z, st.in1), st.s);
    const float f2 = fmaf(DT_C, st.s, st.f);
    const float v2 = fmaf(C.c_vl, st.fv, st.v);
    const float q2 = fmaf(C.c_vl, st.qd, st.q);

    const float u = f2 - 1.0f;
    float p = fmaf(C.g4, u, C.g3);
    p       = fmaf(p,   u, C.g2);
    p       = fmaf(p,   u, C.g1);
    const float G = fmaf(p, u, C.g0);
    st.G   = G;
    st.in1 = fmaf(-C.mu, u, -C.sigma * s2);
    st.fv  = f2 - v2;
    st.qd  = G - q2;

    st.s = s2; st.f = f2; st.v = v2; st.q = q2;
    return make_float2(v2, q2);
}

// Readout: identical ops/bits to R9, executed one chunk later.
__device__ __forceinline__ float bw_readout(const BWConst& C, float pv, float pq)
{
    const float rv = fast_rcp(pv);
    const float t0 = fmaf(-C.C3, pv, C.C0);
    const float t1 = fmaf(-C.C1, pq, t0);
    return fmaf(-C.C2 * pq, rv, t1);
}

template<int U, int BS>
__global__ __launch_bounds__(128, 1)
void bw_bold_kernel(const float* __restrict__ noise,
                    const float* __restrict__ sigma_p,
                    const float* __restrict__ mu_p,
                    const float* __restrict__ lamb_p,
                    const float* __restrict__ beta_p,
                    const float* __restrict__ psi_p,
                    const float* __restrict__ phi_p,
                    const float* __restrict__ chi_p,
                    float* __restrict__ out,
                    int T)
{
    const int gid = blockIdx.x * blockDim.x + threadIdx.x;

    BWConst C;
    C.sigma = __ldg(sigma_p);
    C.mu    = __ldg(mu_p);
    const float lamb = __ldg(lamb_p);
    const float beta = __ldg(beta_p);
    const float psi  = __ldg(psi_p);
    const float phi  = __ldg(phi_p);
    const float chi  = __ldg(chi_p);
    C.c_vl  = DT_C / lamb;
    C.C0    = V0_C * (phi + psi + chi);
    C.C1    = V0_C * phi;
    C.C2    = V0_C * psi;
    C.C3    = V0_C * chi;

    // One-time double-precision Taylor coefficients for
    // G(u) = (1+u)*E(1+u)/beta, E(f) = 1 - exp(ln(1-beta)/f).
    {
        const double bd  = (double)beta;
        const double c   = log(1.0 - bd);
        const double omb = 1.0 - bd;
        double a[6], A[6], e[6];
        a[0] = 0.0;
        #pragma unroll
        for (int k = 1; k < 6; k++) a[k] = (k & 1) ? -c : c;
        A[0] = 1.0;
        #pragma unroll
        for (int k = 0; k < 5; k++) {
            double sum = 0.0;
            #pragma unroll
            for (int j = 0; j <= k; j++) sum += (double)(j + 1) * a[j + 1] * A[k - j];
            A[k + 1] = sum / (double)(k + 1);
        }
        e[0] = 1.0 - omb * A[0];
        #pragma unroll
        for (int k = 1; k < 6; k++) e[k] = -omb * A[k];
        const double ibd = 1.0 / bd;
        C.g0 = (float)(e[0] * ibd);
        C.g1 = (float)((e[1] + e[0]) * ibd);
        C.g2 = (float)((e[2] + e[1]) * ibd);
        C.g3 = (float)((e[3] + e[2]) * ibd);
        C.g4 = (float)((e[4] + e[3]) * ibd);
    }

    BWState st;
    st.s = 0.0f; st.f = 1.0f; st.v = 1.0f; st.q = 1.0f;
    st.G   = C.g0;                       // u = 0
    st.in1 = fmaf(-C.mu, 0.0f, -C.sigma * 0.0f);
    st.fv  = st.f - st.v;                // 0
    st.qd  = st.G - st.q;                // g0 - 1

    const float* np = noise + gid;
    float*       op = out   + gid;

    const int nch = T / U;

    float bufA[U], bufB[U];
    float pendV[U], pendQ[U];

    // ---- Prologue: load chunks 0,1; run chunk 0 fronts (no readouts),
    //      prefetching chunk 2 into bufA as its slots free up. ----
    if (nch > 0) {
        #pragma unroll
        for (int i = 0; i < U; i++) bufA[i] = np[(size_t)i * BS];
        if (nch > 1) {
            #pragma unroll
            for (int i = 0; i < U; i++) bufB[i] = np[(size_t)(U + i) * BS];
        }
        const float* pp2 = np + (size_t)2 * U * BS;
        #pragma unroll
        for (int i = 0; i < U; i++) {
            const float2 vq = bw_front(st, C, bufA[i]);
            pendV[i] = vq.x; pendQ[i] = vq.y;
            if (nch > 2) bufA[i] = pp2[(size_t)i * BS];
        }
    }

    // ---- Main loop: chunk c fronts + chunk c-1 readouts + chunk c+2 LDGs,
    //      all interleaved per unrolled step. ----
    for (int c = 1; c < nch; c++) {
        const bool odd = (c & 1) != 0;
        float*       oprev = op + (size_t)(c - 1) * U * BS;
        const float* pnext = np + (size_t)(c + 2) * U * BS;
        const bool   pf    = (c + 2 < nch);
        #pragma unroll
        for (int i = 0; i < U; i++) {
            // independent gap-filler: lagged readout + store
            oprev[(size_t)i * BS] = bw_readout(C, pendV[i], pendQ[i]);
            // dependent front for this chunk
            const float2 vq = bw_front(st, C, odd ? bufB[i] : bufA[i]);
            pendV[i] = vq.x; pendQ[i] = vq.y;
            // independent gap-filler: prefetch chunk c+2 into the buffer
            // slot just consumed
            if (pf) {
                if (odd) bufB[i] = pnext[(size_t)i * BS];
                else     bufA[i] = pnext[(size_t)i * BS];
            }
        }
    }

    // ---- Epilogue: flush readouts of the last chunk. ----
    if (nch > 0) {
        float* olast = op + (size_t)(nch - 1) * U * BS;
        #pragma unroll
        for (int i = 0; i < U; i++)
            olast[(size_t)i * BS] = bw_readout(C, pendV[i], pendQ[i]);
    }

    // ---- Tail (T not divisible by U): sequential, immediate readout. ----
    for (int t = nch * U; t < T; t++) {
        const float2 vq = bw_front(st, C, np[(size_t)t * BS]);
        op[(size_t)t * BS] = bw_readout(C, vq.x, vq.y);
    }
}

extern "C" void kernel_launch(void* const* d_in, const int* in_sizes, int n_in,
                              void* d_out, int out_size)
{
    const float* noise = (const float*)d_in[0];
    const int T = in_sizes[0] / BATCH_C;

    const int threads = 128;
    const int blocks  = BATCH_C / threads;   // 128 blocks x 128 thr = 1 warp/SMSP

    bw_bold_kernel<20, BATCH_C><<<blocks, threads>>>(
        noise,
        (const float*)d_in[1], (const float*)d_in[2],
        (const float*)d_in[3], (const float*)d_in[4],
        (const float*)d_in[5], (const float*)d_in[6],
        (const float*)d_in[7],
        (float*)d_out, T);
}

// round 13
// speedup vs baseline: 1.2887x; 1.2887x over previous
#include <cuda_runtime.h>
#include <cuda_bf16.h>

// Balloon-Windkessel BOLD, explicit Euler, T=1000 steps, B=16384 sims.
// R13 = R9 structure with ZERO MUFU in the hot loop:
//  - rv ~= 1/v carried as state, refreshed by one Newton step per Euler step:
//    rv' = rv*(2 - v2*rv). v moves ~3e-4/step -> steady-state rel err
//    (dv/v)^2 ~ 1e-7, as good as rcp.approx, readout-only.
//    Rationale: MUFU is the only variable-latency (scoreboard-tracked) ALU op
//    in the loop; per-step time (~90cyc) has been invariant to FMA count,
//    warp count, and readout placement -> exposed SB waits are the suspect.
//  - s-update folded to a 4-cycle cycle: s2 = fma(a0, s, drv), drv staged
//    (a0 = 1-DT*sigma, a1 = DT*NA, b2u = -DT*mu*u). Isolated small-state fold.
//  - f,v,q recurrences + staging identical to R9 (rel_err 1.14e-4 path).

#define DT_C        0.01f
#define V0_C        0.02f
#define NOISE_AMP_C 0.01f
#define BATCH_C     16384

struct BWState {
    float s, f, v, q;
    float rv;    // running 1/v estimate (Newton-refreshed)
    float b2u;   // -DT*mu*u            (staged)
    float fv;    // f - v               (staged)
    float qd;    // G - q               (staged)
};

struct BWConst {
    float a0, a1;                // s-decay, noise gain
    float na2;                   // -DT*mu
    float c_vl;
    float C0, C1, C2, C3;        // readout constants
    float g0, g1, g2, g3, g4;    // G(u) Taylor coefficients (deg 4)
};

// One Euler step. f,v,q carried arithmetic identical to R9.
__device__ __forceinline__ float bw_step(BWState& st, const BWConst& C, float z)
{
    // Front: all inputs staged or state; every cycle is 4-8 cycles.
    const float s2 = fmaf(C.a0, st.s, fmaf(C.a1, z, st.b2u));
    const float f2 = fmaf(DT_C, st.s, st.f);
    const float v2 = fmaf(C.c_vl, st.fv, st.v);
    const float q2 = fmaf(C.c_vl, st.qd, st.q);

    // Newton refresh of 1/v (no MUFU): rv2 = rv*(2 - v2*rv)
    const float tN  = fmaf(-v2, st.rv, 2.0f);
    const float rv2 = st.rv * tN;

    // Staging for the NEXT step (pure functions of s2,f2,v2,q2):
    const float u = f2 - 1.0f;
    float p = fmaf(C.g4, u, C.g3);
    p       = fmaf(p,   u, C.g2);
    p       = fmaf(p,   u, C.g1);
    const float G = fmaf(p, u, C.g0);
    st.b2u = C.na2 * u;
    st.fv  = f2 - v2;
    st.qd  = G - q2;

    // Readout: y = C0 - C1*q2 - C3*v2 - (C2*q2)*rv2
    const float t0 = fmaf(-C.C3, v2, C.C0);
    const float t1 = fmaf(-C.C1, q2, t0);
    const float y  = fmaf(-C.C2 * q2, rv2, t1);

    st.s = s2; st.f = f2; st.v = v2; st.q = q2; st.rv = rv2;
    return y;
}

template<int U, int BS>
__global__ __launch_bounds__(128, 1)
void bw_bold_kernel(const float* __restrict__ noise,
                    const float* __restrict__ sigma_p,
                    const float* __restrict__ mu_p,
                    const float* __restrict__ lamb_p,
                    const float* __restrict__ beta_p,
                    const float* __restrict__ psi_p,
                    const float* __restrict__ phi_p,
                    const float* __restrict__ chi_p,
                    float* __restrict__ out,
                    int T)
{
    const int gid = blockIdx.x * blockDim.x + threadIdx.x;

    const float sigma = __ldg(sigma_p);
    const float mu    = __ldg(mu_p);
    const float lamb  = __ldg(lamb_p);
    const float beta  = __ldg(beta_p);
    const float psi   = __ldg(psi_p);
    const float phi   = __ldg(phi_p);
    const float chi   = __ldg(chi_p);

    BWConst C;
    C.a0   = 1.0f - DT_C * sigma;
    C.a1   = DT_C * NOISE_AMP_C;
    C.na2  = -DT_C * mu;
    C.c_vl = DT_C / lamb;
    C.C0   = V0_C * (phi + psi + chi);
    C.C1   = V0_C * phi;
    C.C2   = V0_C * psi;
    C.C3   = V0_C * chi;

    // One-time double-precision Taylor coefficients for
    // G(u) = (1+u)*E(1+u)/beta, E(f) = 1 - exp(ln(1-beta)/f).
    {
        const double bd  = (double)beta;
        const double c   = log(1.0 - bd);
        const double omb = 1.0 - bd;
        double a[6], A[6], e[6];
        a[0] = 0.0;
        #pragma unroll
        for (int k = 1; k < 6; k++) a[k] = (k & 1) ? -c : c;
        A[0] = 1.0;
        #pragma unroll
        for (int k = 0; k < 5; k++) {
            double sum = 0.0;
            #pragma unroll
            for (int j = 0; j <= k; j++) sum += (double)(j + 1) * a[j + 1] * A[k - j];
            A[k + 1] = sum / (double)(k + 1);
        }
        e[0] = 1.0 - omb * A[0];
        #pragma unroll
        for (int k = 1; k < 6; k++) e[k] = -omb * A[k];
        const double ibd = 1.0 / bd;
        C.g0 = (float)(e[0] * ibd);
        C.g1 = (float)((e[1] + e[0]) * ibd);
        C.g2 = (float)((e[2] + e[1]) * ibd);
        C.g3 = (float)((e[3] + e[2]) * ibd);
        C.g4 = (float)((e[4] + e[3]) * ibd);
    }

    BWState st;
    st.s = 0.0f; st.f = 1.0f; st.v = 1.0f; st.q = 1.0f;
    st.rv  = 1.0f;               // exact 1/v0
    st.b2u = C.na2 * 0.0f;       // u0 = 0
    st.fv  = 0.0f;               // f0 - v0
    st.qd  = C.g0 - 1.0f;        // G(f0) - q0

    const float* np = noise + gid;
    float*       op = out   + gid;

    const int nch = T / U;

    float bufA[U], bufB[U];
    if (nch > 0) {
        #pragma unroll
        for (int i = 0; i < U; i++) bufA[i] = np[(size_t)i * BS];
    }

    int c = 0;
    for (; c + 1 < nch; c += 2) {
        {   // prefetch chunk c+1
            const float* pp = np + (size_t)(c + 1) * U * BS;
            #pragma unroll
            for (int i = 0; i < U; i++) bufB[i] = pp[(size_t)i * BS];
        }
        {   // compute chunk c
            float* o = op + (size_t)c * U * BS;
            #pragma unroll
            for (int i = 0; i < U; i++)
                o[(size_t)i * BS] = bw_step(st, C, bufA[i]);
        }
        if (c + 2 < nch) {   // prefetch chunk c+2
            const float* pp = np + (size_t)(c + 2) * U * BS;
            #pragma unroll
            for (int i = 0; i < U; i++) bufA[i] = pp[(size_t)i * BS];
        }
        {   // compute chunk c+1
            float* o = op + (size_t)(c + 1) * U * BS;
            #pragma unroll
            for (int i = 0; i < U; i++)
                o[(size_t)i * BS] = bw_step(st, C, bufB[i]);
        }
    }
    if (c < nch) {  // odd trailing chunk
        float* o = op + (size_t)c * U * BS;
        #pragma unroll
        for (int i = 0; i < U; i++)
            o[(size_t)i * BS] = bw_step(st, C, bufA[i]);
        c++;
    }

    // Tail (T not divisible by U).
    for (int t = nch * U; t < T; t++) {
        op[(size_t)t * BS] = bw_step(st, C, np[(size_t)t * BS]);
    }
}

extern "C" void kernel_launch(void* const* d_in, const int* in_sizes, int n_in,
                              void* d_out, int out_size)
{
    const float* noise = (const float*)d_in[0];
    const int T = in_sizes[0] / BATCH_C;

    const int threads = 128;
    const int blocks  = BATCH_C / threads;   // 128 blocks x 128 thr = 1 warp/SMSP

    bw_bold_kernel<20, BATCH_C><<<blocks, threads>>>(
        noise,
        (const float*)d_in[1], (const float*)d_in[2],
        (const float*)d_in[3], (const float*)d_in[4],
        (const float*)d_in[5], (const float*)d_in[6],
        (const float*)d_in[7],
        (float*)d_out, T);
}